// round 8
// baseline (speedup 1.0000x reference)
#include <cuda_runtime.h>

// Dense_RBS_density_3D: rho_out = W rho W^T, W = 39 sparse Givens layers
// (38 disjoint 2x2 column rotations each) on the C(40,2)=780-dim basis.
// K(M) = (M W^T)^T = W M^T applied twice => W rho W^T. Two launches with a
// private __device__ scratch between.
//
// R8 vs R7: tile 30->20 rows => 62.5 KB smem => 3 CTAs/SM (occ 48%->72%).
// Per-warp rotate work identical (2 rows/warp, 80 items); pure latency hiding.
// launch_bounds(512,3) caps regs at 42; load unroll reduced to fit.

#define DD      780
#define NGATES  39
#define NBATCH  64
#define RROWS   20            // rows per tile
#define NTILES  39            // 780 / 20
#define STRIDE  781           // odd -> conflict-free transposed smem reads
#define THREADS 512
#define RWARPS  10            // rotate warps (2 rows each)
#define TILE2   (RROWS * DD / 2)                 // 7800 float2 per tile
#define TILE2_FULL ((TILE2 / THREADS) * THREADS) // 7680

__device__ float g_tmp[(size_t)NBATCH * DD * DD];  // 155.7 MB scratch

__device__ __forceinline__ int pair_rank(int p, int q) {  // p<q, 40 qubits
    return p * 39 - (p * (p - 1)) / 2 + (q - p - 1);
}

__device__ __forceinline__ void rbs_body(const float* __restrict__ in,
                                         float* __restrict__ out,
                                         const float* __restrict__ angles) {
    extern __shared__ float tile[];                 // RROWS * STRIDE
    __shared__ float s_cos[NGATES], s_sin[NGATES];
    __shared__ unsigned int s_oij[NGATES * 40];     // oi*4 | (oj*4 << 16)

    const int tid = threadIdx.x;
    const int b   = blockIdx.x / NTILES;
    const int t   = blockIdx.x - b * NTILES;
    const int r0  = t * RROWS;

    if (tid < NGATES) {
        float th = angles[tid];
        s_cos[tid] = cosf(th);
        s_sin[tid] = sinf(th);
    }
    // offset table: gate g, pair-index x (x != g, g+1):
    //   oi = 4*rank({g,x}), oj = 4*rank({g+1,x})
    for (int n = tid; n < NGATES * 40; n += THREADS) {
        int g = n / 40, x = n - 40 * g;
        unsigned int v = 0;
        if (x != g && x != g + 1) {
            int i = (x < g)     ? pair_rank(x, g)     : pair_rank(g, x);
            int j = (x < g + 1) ? pair_rank(x, g + 1) : pair_rank(g + 1, x);
            v = (unsigned int)(i * 4) | ((unsigned int)(j * 4) << 16);
        }
        s_oij[n] = v;
    }

    // ---------- load: rows [r0,r0+20) contiguous in gmem; float2 ----------
    {
        const float2* src2 = (const float2*)(in + (size_t)b * DD * DD
                                                + (size_t)r0 * DD);
        #pragma unroll 5
        for (int k = 0; k < TILE2_FULL / THREADS; k++) {     // 15 uniform iters
            int n   = tid + k * THREADS;
            int row = n / (DD / 2);
            int c2  = n - row * (DD / 2);
            float2 v = __ldg(src2 + n);
            float* d = &tile[row * STRIDE + 2 * c2];
            d[0] = v.x; d[1] = v.y;
        }
        int n = tid + TILE2_FULL;                            // tail: 120 threads
        if (n < TILE2) {
            int row = n / (DD / 2);
            int c2  = n - row * (DD / 2);
            float2 v = __ldg(src2 + n);
            float* d = &tile[row * STRIDE + 2 * c2];
            d[0] = v.x; d[1] = v.y;
        }
    }
    __syncthreads();

    // ---------- rotate: warp-autonomous, frontier-carry, 2 rows/warp ------
    {
        const int w    = tid >> 5;
        const int lane = tid & 31;
        if (w < RWARPS) {
            // item n = 32k+lane in [0,80): x = n>>1 (0..39), row = n&1
            int   xk[3];
            char* rp[3];
            bool  act[3];
            float carry[3];
            #pragma unroll
            for (int k = 0; k < 3; k++) {
                int n = 32 * k + lane;
                act[k]   = (n < 80);
                xk[k]    = n >> 1;
                rp[k]    = (char*)&tile[(2 * w + (n & 1)) * STRIDE];
                carry[k] = 0.0f;
            }
            #pragma unroll 1
            for (int g = 0; g < NGATES; g++) {
                const float cg = s_cos[g], sg = s_sin[g];
                const unsigned int* go = &s_oij[g * 40];
                #pragma unroll
                for (int k = 0; k < 3; k++) {
                    const int x = xk[k];
                    if (act[k] && x != g && x != g + 1) {    // active this gate
                        unsigned int oij = go[x];
                        float* pi = (float*)(rp[k] + (oij & 0xFFFFu));
                        float* pj = (float*)(rp[k] + (oij >> 16));
                        float xj = *pj;
                        float xi = (g == 0 || g == x + 1) ? *pi : carry[k];
                        *pi = cg * xi - sg * xj;             // done: {g,x}
                        float nj = sg * xi + cg * xj;        // frontier {g+1,x}
                        carry[k] = nj;
                        if (g == x - 2 || g == NGATES - 1)   // segment end
                            *pj = nj;                        // flush frontier
                    }
                }
                __syncwarp();
            }
        }
    }
    __syncthreads();

    // ---------- transposed store: out[b, col, r0+row], coalesced ----------
    {
        float* dstb = out + (size_t)b * DD * DD + r0;
        #pragma unroll 4
        for (int n = tid; n < DD * RROWS; n += THREADS) {
            int col = n / RROWS;
            int row = n - col * RROWS;
            dstb[(size_t)col * DD + row] = tile[row * STRIDE + col];
        }
    }
}

__global__ __launch_bounds__(THREADS, 3)
void rbs_pass1(const float* __restrict__ in, const float* __restrict__ angles) {
    rbs_body(in, g_tmp, angles);
}

__global__ __launch_bounds__(THREADS, 3)
void rbs_pass2(float* __restrict__ out, const float* __restrict__ angles) {
    rbs_body(g_tmp, out, angles);
}

extern "C" void kernel_launch(void* const* d_in, const int* in_sizes, int n_in,
                              void* d_out, int out_size) {
    const float* input_state = (const float*)d_in[0];  // [64,780,780] f32
    const float* angles      = (const float*)d_in[1];  // [39] f32
    float* out = (float*)d_out;

    const int smem = RROWS * STRIDE * sizeof(float);   // 62,480 B dynamic
    cudaFuncSetAttribute(rbs_pass1, cudaFuncAttributeMaxDynamicSharedMemorySize, smem);
    cudaFuncSetAttribute(rbs_pass2, cudaFuncAttributeMaxDynamicSharedMemorySize, smem);

    dim3 grid(NBATCH * NTILES);   // 2496 blocks
    rbs_pass1<<<grid, THREADS, smem>>>(input_state, angles);
    rbs_pass2<<<grid, THREADS, smem>>>(out, angles);
}

// round 9
// speedup vs baseline: 1.2400x; 1.2400x over previous
#include <cuda_runtime.h>

// Dense_RBS_density_3D: rho_out = W rho W^T, W = 39 sparse Givens layers
// (38 disjoint 2x2 column rotations each) on the C(40,2)=780-dim basis.
// K(M) = (M W^T)^T = W M^T applied twice => W rho W^T. Two launches with a
// private __device__ scratch between.
//
// R9 vs R7 (same geometry: 30-row stride-781 tiles, 512 thr, 2 CTAs/SM):
//  (1) TABLE-FREE rotate: for fixed pair-index x the i-offset follows an
//      arithmetic walk: step = (g <= x-1) ? 38-g : 1, and j = i + step's
//      data-phase value (38-g in B-phase, 1 in A-phase). Removes the per-block
//      1560-entry offset table and its per-gate LDS + unpack ALU.
//  (2) store loop writes STG.64 (2 rows/item): half the store instructions.

#define DD      780
#define NGATES  39
#define NBATCH  64
#define RROWS   30            // rows per tile
#define NTILES  26            // 780 / 30
#define STRIDE  781           // odd -> conflict-free transposed smem reads
#define THREADS 512
#define HR      (RROWS / 2)   // 15 row-pairs for the float2 store
#define TILE2   (RROWS * DD / 2)                 // 11700 float2 per tile
#define TILE2_FULL ((TILE2 / THREADS) * THREADS) // 11264

__device__ float g_tmp[(size_t)NBATCH * DD * DD];  // 155.7 MB scratch

__device__ __forceinline__ void rbs_body(const float* __restrict__ in,
                                         float* __restrict__ out,
                                         const float* __restrict__ angles) {
    extern __shared__ float tile[];                 // RROWS * STRIDE
    __shared__ float s_cos[NGATES], s_sin[NGATES];

    const int tid = threadIdx.x;
    const int b   = blockIdx.x / NTILES;
    const int t   = blockIdx.x - b * NTILES;
    const int r0  = t * RROWS;

    if (tid < NGATES) {
        float th = angles[tid];
        s_cos[tid] = cosf(th);
        s_sin[tid] = sinf(th);
    }

    // ---------- load: rows [r0,r0+30) contiguous in gmem; float2 ----------
    {
        const float2* src2 = (const float2*)(in + (size_t)b * DD * DD
                                                + (size_t)r0 * DD);
        #pragma unroll 11
        for (int k = 0; k < TILE2_FULL / THREADS; k++) {     // 22 uniform iters
            int n   = tid + k * THREADS;
            int row = n / (DD / 2);
            int c2  = n - row * (DD / 2);
            float2 v = __ldg(src2 + n);
            float* d = &tile[row * STRIDE + 2 * c2];
            d[0] = v.x; d[1] = v.y;
        }
        int n = tid + TILE2_FULL;                            // tail: 436 threads
        if (n < TILE2) {
            int row = n / (DD / 2);
            int c2  = n - row * (DD / 2);
            float2 v = __ldg(src2 + n);
            float* d = &tile[row * STRIDE + 2 * c2];
            d[0] = v.x; d[1] = v.y;
        }
    }
    __syncthreads();

    // ---------- rotate: warp-autonomous, frontier-carry, table-free -------
    // item n = 32k+lane in [0,80): x = n>>1 (pair-index 0..39), row = n&1.
    // Offset walk (verified x=0,1,2,5,38,39):
    //   off init = x-1; per gate: data step d = (g < x-1) ? 38-g : 1;
    //   update step u = (g <= x-1) ? 38-g : 1; active iff g<x-1 or g>x;
    //   fresh-load xi at g==0 or g==x+1; flush carry at g==x-2 or g==38.
    {
        const int w    = tid >> 5;
        const int lane = tid & 31;
        if (w < 15) {
            int    xk[3], xm1[3], off[3];
            float* rp[3];
            float  carry[3];
            bool   act[3];
            #pragma unroll
            for (int k = 0; k < 3; k++) {
                int n  = 32 * k + lane;
                act[k] = (n < 80);
                int x  = n >> 1;
                xk[k]  = x;
                xm1[k] = x - 1;
                off[k] = x - 1;
                rp[k]  = &tile[(2 * w + (n & 1)) * STRIDE];
                carry[k] = 0.0f;
            }
            #pragma unroll 1
            for (int g = 0; g < NGATES; g++) {
                const float cg = s_cos[g], sg = s_sin[g];
                const bool  g0 = (g == 0), gLast = (g == NGATES - 1);
                #pragma unroll
                for (int k = 0; k < 3; k++) {
                    const int  x    = xk[k];
                    const bool inB  = (g <  xm1[k]);
                    const bool le   = (g <= xm1[k]);
                    const int  bs   = 38 - g;
                    if (act[k] && (inB || g > x)) {
                        const int step = inB ? bs : 1;
                        float* pi = rp[k] + off[k];
                        float* pj = pi + step;
                        float  xj = *pj;
                        float  xi = (g0 || g == x + 1) ? *pi : carry[k];
                        *pi = cg * xi - sg * xj;             // done: {min,max}
                        float nj = sg * xi + cg * xj;        // frontier
                        carry[k] = nj;
                        if (g == x - 2 || gLast)             // segment end
                            *pj = nj;
                    }
                    off[k] += le ? bs : 1;
                }
                __syncwarp();
            }
        }
    }
    __syncthreads();

    // ---------- transposed store: out[b, col, r0+2*r2 .. +1], STG.64 ------
    {
        float* dstb = out + (size_t)b * DD * DD + r0;
        #pragma unroll 4
        for (int n = tid; n < DD * HR; n += THREADS) {
            int col = n / HR;
            int r2  = n - col * HR;
            float2 v;
            v.x = tile[(2 * r2 + 0) * STRIDE + col];
            v.y = tile[(2 * r2 + 1) * STRIDE + col];
            *(float2*)(dstb + (size_t)col * DD + 2 * r2) = v;
        }
    }
}

__global__ __launch_bounds__(THREADS, 2)
void rbs_pass1(const float* __restrict__ in, const float* __restrict__ angles) {
    rbs_body(in, g_tmp, angles);
}

__global__ __launch_bounds__(THREADS, 2)
void rbs_pass2(float* __restrict__ out, const float* __restrict__ angles) {
    rbs_body(g_tmp, out, angles);
}

extern "C" void kernel_launch(void* const* d_in, const int* in_sizes, int n_in,
                              void* d_out, int out_size) {
    const float* input_state = (const float*)d_in[0];  // [64,780,780] f32
    const float* angles      = (const float*)d_in[1];  // [39] f32
    float* out = (float*)d_out;

    const int smem = RROWS * STRIDE * sizeof(float);   // 93,720 B dynamic
    cudaFuncSetAttribute(rbs_pass1, cudaFuncAttributeMaxDynamicSharedMemorySize, smem);
    cudaFuncSetAttribute(rbs_pass2, cudaFuncAttributeMaxDynamicSharedMemorySize, smem);

    dim3 grid(NBATCH * NTILES);   // 1664 blocks
    rbs_pass1<<<grid, THREADS, smem>>>(input_state, angles);
    rbs_pass2<<<grid, THREADS, smem>>>(out, angles);
}

// round 10
// speedup vs baseline: 1.4534x; 1.1722x over previous
#include <cuda_runtime.h>

// Dense_RBS_density_3D: rho_out = W rho W^T, W = 39 sparse Givens layers
// (38 disjoint 2x2 column rotations each) on the C(40,2)=780-dim basis.
// K(M) = (M W^T)^T = W M^T applied twice => W rho W^T. Two launches with a
// private __device__ scratch between.
//
// R10 vs R9 (same geometry: 30 rows/tile, 512 thr, 2 CTAs/SM, 93.7 KB smem):
// the two rows a warp owns are INTERLEAVED as float2 lanes in smem, so each
// rotation item processes both rows with 1 LDS.64 + 1 STS.64 + 4 f32x2
// FMA/MUL (PTX packed path) and pays the offset-walk/predicate cost once for
// 2 rotations. Offset walk + frontier carry are verbatim R9 (proven), with
// the carry now a packed 64-bit register.

#define DD      780
#define NGATES  39
#define NBATCH  64
#define RROWS   30            // rows per tile
#define NPR     15            // pair-rows (float2 lanes)
#define NTILES  26            // 780 / 30
#define STRIDE2 781           // float2 stride per pair-row (odd)
#define THREADS 512
#define NITEMS  (NPR * DD)                       // 11700 load/store items
#define NFULL   ((NITEMS / THREADS) * THREADS)   // 11264

__device__ float g_tmp[(size_t)NBATCH * DD * DD];  // 155.7 MB scratch

typedef unsigned long long u64;

__device__ __forceinline__ u64 f2pack(float lo, float hi) {
    u64 r; asm("mov.b64 %0, {%1, %2};" : "=l"(r) : "f"(lo), "f"(hi)); return r;
}
__device__ __forceinline__ u64 f2mul(u64 a, u64 b) {
    u64 r; asm("mul.rn.f32x2 %0, %1, %2;" : "=l"(r) : "l"(a), "l"(b)); return r;
}
__device__ __forceinline__ u64 f2fma(u64 a, u64 b, u64 c) {
    u64 r; asm("fma.rn.f32x2 %0, %1, %2, %3;" : "=l"(r) : "l"(a), "l"(b), "l"(c));
    return r;
}

__device__ __forceinline__ void rbs_body(const float* __restrict__ in,
                                         float* __restrict__ out,
                                         const float* __restrict__ angles) {
    extern __shared__ u64 tile2[];                  // NPR * STRIDE2 float2
    __shared__ float s_cos[NGATES], s_sin[NGATES];

    const int tid = threadIdx.x;
    const int b   = blockIdx.x / NTILES;
    const int t   = blockIdx.x - b * NTILES;
    const int r0  = t * RROWS;

    if (tid < NGATES) {
        float th = angles[tid];
        s_cos[tid] = cosf(th);
        s_sin[tid] = sinf(th);
    }

    // ---------- load: interleave rows 2pr, 2pr+1 into float2 lanes --------
    {
        const float* src = in + (size_t)b * DD * DD + (size_t)r0 * DD;
        #pragma unroll 11
        for (int k = 0; k < NFULL / THREADS; k++) {          // 22 uniform iters
            int n  = tid + k * THREADS;
            int pr = n / DD;
            int c  = n - pr * DD;
            float a0 = __ldg(src + (size_t)(2 * pr)     * DD + c);
            float a1 = __ldg(src + (size_t)(2 * pr + 1) * DD + c);
            tile2[pr * STRIDE2 + c] = f2pack(a0, a1);
        }
        int n = tid + NFULL;                                 // tail: 436 threads
        if (n < NITEMS) {
            int pr = n / DD;
            int c  = n - pr * DD;
            float a0 = __ldg(src + (size_t)(2 * pr)     * DD + c);
            float a1 = __ldg(src + (size_t)(2 * pr + 1) * DD + c);
            tile2[pr * STRIDE2 + c] = f2pack(a0, a1);
        }
    }
    __syncthreads();

    // ---------- rotate: warp-autonomous, frontier-carry, table-free -------
    // Offset walk (proven in R9): off init = x-1; per gate:
    //   data step = (g < x-1) ? 38-g : 1; update step = (g <= x-1) ? 38-g : 1;
    //   active iff g < x-1 or g > x; fresh-load xi at g==0 or g==x+1;
    //   flush carry at g==x-2 or g==38. Payload is float2 (both rows).
    {
        const int w    = tid >> 5;
        const int lane = tid & 31;
        if (w < NPR) {
            u64* rp = &tile2[w * STRIDE2];
            const int  x0 = lane,      x1 = 32 + lane;       // two item slots
            const bool a1 = (lane < 8);                      // x1 in [32,40)
            int off0 = x0 - 1, off1 = x1 - 1;
            u64 carry0 = 0, carry1 = 0;

            #pragma unroll 1
            for (int g = 0; g < NGATES; g++) {
                const u64  c2  = f2pack(s_cos[g],  s_cos[g]);
                const u64  s2  = f2pack(s_sin[g],  s_sin[g]);
                const u64  ns2 = f2pack(-s_sin[g], -s_sin[g]);
                const int  bs  = 38 - g;
                const bool g0  = (g == 0), gLast = (g == NGATES - 1);

                #define DOIT(X, OFF, CARRY, ACT)  {                        \
                    const bool inB = (g < (X) - 1);                        \
                    if ((ACT) && (inB || g > (X))) {                       \
                        const int step = inB ? bs : 1;                     \
                        u64* pi = rp + (OFF);                              \
                        u64* pj = pi + step;                               \
                        u64 xj = *pj;                                      \
                        u64 xi = (g0 || g == (X) + 1) ? *pi : (CARRY);     \
                        *pi = f2fma(c2, xi, f2mul(ns2, xj));               \
                        u64 nj = f2fma(s2, xi, f2mul(c2, xj));             \
                        (CARRY) = nj;                                      \
                        if (g == (X) - 2 || gLast) *pj = nj;               \
                    }                                                      \
                    (OFF) += (g <= (X) - 1) ? bs : 1; }

                DOIT(x0, off0, carry0, true)
                DOIT(x1, off1, carry1, a1)
                #undef DOIT
                __syncwarp();
            }
        }
    }
    __syncthreads();

    // ---------- transposed store: out[b, col, r0+2pr..+1], STG.64 ---------
    {
        float* dstb = out + (size_t)b * DD * DD + r0;
        #pragma unroll 4
        for (int n = tid; n < NITEMS; n += THREADS) {
            int col = n / NPR;
            int pr  = n - col * NPR;
            u64 v = tile2[pr * STRIDE2 + col];               // LDS.64
            *(u64*)(dstb + (size_t)col * DD + 2 * pr) = v;   // STG.64
        }
    }
}

__global__ __launch_bounds__(THREADS, 2)
void rbs_pass1(const float* __restrict__ in, const float* __restrict__ angles) {
    rbs_body(in, g_tmp, angles);
}

__global__ __launch_bounds__(THREADS, 2)
void rbs_pass2(float* __restrict__ out, const float* __restrict__ angles) {
    rbs_body(g_tmp, out, angles);
}

extern "C" void kernel_launch(void* const* d_in, const int* in_sizes, int n_in,
                              void* d_out, int out_size) {
    const float* input_state = (const float*)d_in[0];  // [64,780,780] f32
    const float* angles      = (const float*)d_in[1];  // [39] f32
    float* out = (float*)d_out;

    const int smem = NPR * STRIDE2 * sizeof(u64);      // 93,720 B dynamic
    cudaFuncSetAttribute(rbs_pass1, cudaFuncAttributeMaxDynamicSharedMemorySize, smem);
    cudaFuncSetAttribute(rbs_pass2, cudaFuncAttributeMaxDynamicSharedMemorySize, smem);

    dim3 grid(NBATCH * NTILES);   // 1664 blocks
    rbs_pass1<<<grid, THREADS, smem>>>(input_state, angles);
    rbs_pass2<<<grid, THREADS, smem>>>(out, angles);
}